// round 16
// baseline (speedup 1.0000x reference)
#include <cuda_runtime.h>
#include <cstdint>

// PoseLSTM v14.1: split-domain wavefront — two named-barrier groups per block
// with an mbarrier handshake at the layer4->layer5 boundary.
//   Block = 448 threads: group A = warps 0-6 (layers 0-4 @ tids 0-199, 24 pads),
//   group B = warps 7-13 (layers 5-9 @ tids 224-423, 24 pads).
//   Each group syncs with bar.sync {1,2},224 — independent lockstep domains.
//   Cross dependency (layer4 writes layer5's input) via mbF/mbE [2 stages]:
//   B's step s gates on A's layer-4 store (late in A's step s-1) -> B runs
//   structurally offset from A, interleaving pipe bursts.
//   Per-thread math identical to v12 (best: 741us).

#define T_ 1024
#define B_ 1024
#define L_ 10
#define H_ 10
#define NB 4
#define NTH 448
#define GRP 224

typedef unsigned long long u64;

template <bool B> struct BoolC { static constexpr bool value = B; };

__device__ __forceinline__ u64 pk2(float lo, float hi) {
    u64 r; asm("mov.b64 %0, {%1,%2};" : "=l"(r) : "f"(lo), "f"(hi)); return r;
}
__device__ __forceinline__ void upk2(u64 v, float& lo, float& hi) {
    asm("mov.b64 {%0,%1}, %2;" : "=f"(lo), "=f"(hi) : "l"(v));
}
__device__ __forceinline__ u64 fma2(u64 a, u64 b, u64 c) {
    u64 d; asm("fma.rn.f32x2 %0, %1, %2, %3;" : "=l"(d) : "l"(a), "l"(b), "l"(c));
    return d;
}
__device__ __forceinline__ u64 mul2(u64 a, u64 b) {
    u64 d; asm("mul.rn.f32x2 %0, %1, %2;" : "=l"(d) : "l"(a), "l"(b));
    return d;
}
__device__ __forceinline__ u64 add2(u64 a, u64 b) {
    u64 d; asm("add.rn.f32x2 %0, %1, %2;" : "=l"(d) : "l"(a), "l"(b));
    return d;
}
__device__ __forceinline__ float tanhap(float x) {
    float r; asm("tanh.approx.f32 %0, %1;" : "=f"(r) : "f"(x)); return r;
}
__device__ __forceinline__ unsigned smem_u32(const void* p) {
    unsigned a;
    asm("{ .reg .u64 t; cvta.to.shared.u64 t, %1; cvt.u32.u64 %0, t; }"
        : "=r"(a) : "l"(p));
    return a;
}
#define MB_INIT(a, n)  asm volatile("mbarrier.init.shared.b64 [%0], %1;" :: "r"(a), "r"(n) : "memory")
#define MB_ARRIVE(a)   asm volatile("mbarrier.arrive.shared.b64 _, [%0];" :: "r"(a) : "memory")
#define MB_WAIT(a, ph) do {                                                      \
    asm volatile(                                                                \
        "{\n\t.reg .pred P;\n\t"                                                 \
        "WL_%=:\n\t"                                                             \
        "mbarrier.try_wait.parity.acquire.cta.shared::cta.b64 P, [%0], %1, 0x989680;\n\t" \
        "@P bra.uni WD_%=;\n\t"                                                  \
        "bra.uni WL_%=;\n\t"                                                     \
        "WD_%=:\n\t}"                                                            \
        :: "r"(a), "r"(ph) : "memory");                                          \
} while (0)

// matvec for one element: 2 gate rows, 4 chains, bias pre-folded
__device__ __forceinline__ void matvec2(const ulonglong2* zz,
                                        const u64* wA, const u64* wB,
                                        u64 biasA2, u64 biasB2,
                                        float& pA, float& pB) {
    ulonglong2 v0 = zz[0], v1 = zz[1], v2 = zz[2], v3 = zz[3], v4 = zz[4];
    u64 a  = fma2(wA[0], v0.x, biasA2);
    u64 a_ = mul2(wA[1], v0.y);
    u64 b  = fma2(wB[0], v0.x, biasB2);
    u64 b_ = mul2(wB[1], v0.y);
    a  = fma2(wA[2], v1.x, a);  a_ = fma2(wA[3], v1.y, a_);
    b  = fma2(wB[2], v1.x, b);  b_ = fma2(wB[3], v1.y, b_);
    a  = fma2(wA[4], v2.x, a);  a_ = fma2(wA[5], v2.y, a_);
    b  = fma2(wB[4], v2.x, b);  b_ = fma2(wB[5], v2.y, b_);
    a  = fma2(wA[6], v3.x, a);  a_ = fma2(wA[7], v3.y, a_);
    b  = fma2(wB[6], v3.x, b);  b_ = fma2(wB[7], v3.y, b_);
    a  = fma2(wA[8], v4.x, a);  a_ = fma2(wA[9], v4.y, a_);
    b  = fma2(wB[8], v4.x, b);  b_ = fma2(wB[9], v4.y, b_);
    u64 sA = add2(a, a_), sB = add2(b, b_);
    float lo, hi;
    upk2(sA, lo, hi); pA = lo + hi;
    upk2(sB, lo, hi); pB = lo + hi;
}

__global__ __launch_bounds__(NTH, 2)
void lstm_pipe14(const float* __restrict__ x,   // (T,B,H)
                 const float* __restrict__ hp,  // (L,B,H)
                 const float* __restrict__ cp,  // (L,B,H)
                 const float* __restrict__ Wih, // (L,4H,H)
                 const float* __restrict__ Whh, // (L,4H,H)
                 const float* __restrict__ bih, // (L,4H)
                 const float* __restrict__ bhh, // (L,4H)
                 float* __restrict__ out)       // ys ++ hn ++ cn
{
    __shared__ __align__(16) float z[2][L_ + 1][NB][24];
    __shared__ __align__(8) u64 mbar[4];   // [0,1]=full stage0/1, [2,3]=empty

    const int tid  = threadIdx.x;
    const int grp  = (tid >= GRP);           // 0 = layers 0-4, 1 = layers 5-9
    const int gtid = tid - grp * GRP;
    const bool real = (gtid < 200);
    const int g2  = real ? gtid : 0;
    const int l   = g2 / 40 + grp * 5;
    const int r   = g2 % 40;
    const int u   = r >> 2;
    const int eh  = (r >> 1) & 1;
    const int gp  = r & 1;
    const int e2  = eh + 2;
    const int em  = gp ? e2 : eh;
    const int bm  = blockIdx.x * NB + em;
    const bool isL4 = real && (l == 4);
    const bool isL5 = real && (l == 5);

    const unsigned mbF0 = smem_u32(&mbar[0]);
    const unsigned mbF1 = smem_u32(&mbar[1]);
    const unsigned mbE0 = smem_u32(&mbar[2]);
    const unsigned mbE1 = smem_u32(&mbar[3]);

    if (tid == 0) {
        MB_INIT(mbF0, 40); MB_INIT(mbF1, 40);
        MB_INIT(mbE0, 40); MB_INIT(mbE1, 40);
    }

    // ---- k-packed register-stationary weights, sigmoid 0.5 folded ----
    const int rowA = l * 40 + gp * 20 + u;
    const int rowB = rowA + 10;
    const float sclA = gp ? 1.0f : 0.5f;
    u64 wA[10], wB[10];
    {
        const float* WiA = Wih + rowA * 10; const float* WhA = Whh + rowA * 10;
        const float* WiB = Wih + rowB * 10; const float* WhB = Whh + rowB * 10;
#pragma unroll
        for (int k = 0; k < 5; ++k) {
            wA[k]     = pk2(sclA * __ldg(WiA + 2 * k), sclA * __ldg(WiA + 2 * k + 1));
            wA[5 + k] = pk2(sclA * __ldg(WhA + 2 * k), sclA * __ldg(WhA + 2 * k + 1));
            wB[k]     = pk2(0.5f * __ldg(WiB + 2 * k), 0.5f * __ldg(WiB + 2 * k + 1));
            wB[5 + k] = pk2(0.5f * __ldg(WhB + 2 * k), 0.5f * __ldg(WhB + 2 * k + 1));
        }
    }
    const u64 biasA2 = pk2(sclA * (bih[rowA] + bhh[rowA]), 0.0f);
    const u64 biasB2 = pk2(0.5f * (bih[rowB] + bhh[rowB]), 0.0f);
    const float cAa = gp ? 0.0f : 0.5f;
    const float cBa = gp ? 1.0f : 0.5f;

    // ---- init state ----
    float cm = cp[(l * B_ + bm) * H_ + u];
    if (real)
        z[l & 1][l][em][10 + u] = hp[(l * B_ + bm) * H_ + u];
    const bool isLdr = real && (l == 0);
    if (isLdr)
        z[0][0][em][u] = x[(size_t)bm * H_ + u];

    __syncthreads();              // init + mbarrier visibility (only full sync)
    if (isL4) MB_ARRIVE(mbF0);    // prime stage-0 full for B's step 0

    const size_t base_hn = (size_t)T_ * B_ * H_;
    const size_t base_cn = base_hn + (size_t)L_ * B_ * H_;

    // ---- one wavefront step ----
    auto stepf = [&](int scur, int par, auto SC) {
        constexpr bool ST = decltype(SC)::value;
        const int t = scur - l;
        const bool act = ST ? true : ((unsigned)t < (unsigned)T_);

        float xl;
        const bool ldrGo = isLdr && (ST ? true : (scur + 1 < T_));
        if (ldrGo)
            xl = x[((size_t)(scur + 1) * B_ + bm) * H_ + u];

        // group-local barrier
        if (grp == 0) asm volatile("bar.sync 1, %0;" :: "n"(GRP) : "memory");
        else          asm volatile("bar.sync 2, %0;" :: "n"(GRP) : "memory");

        // B gate: layer-5 lanes wait for A's layer-4 store (step scur-1)
        if (isL5) {
            const unsigned mb = par ? mbF1 : mbF0;
            MB_WAIT(mb, (scur >> 1) & 1);
        }

        const ulonglong2* zzA =
            reinterpret_cast<const ulonglong2*>(&z[par][l][eh][0]);
        const ulonglong2* zzB =
            reinterpret_cast<const ulonglong2*>(&z[par][l][e2][0]);

        float pA, pB, qA, qB;
        matvec2(zzA, wA, wB, biasA2, biasB2, pA, pB);
        matvec2(zzB, wA, wB, biasA2, biasB2, qA, qB);

        float vA  = fmaf(cBa,  tanhap(pA), cAa);
        float vB  = fmaf(0.5f, tanhap(pB), 0.5f);
        float vA2 = fmaf(cBa,  tanhap(qA), cAa);
        float vB2 = fmaf(0.5f, tanhap(qB), 0.5f);

        // layer-5 reads done -> release the buffer back to A
        if (isL5) {
            const unsigned mb = par ? mbE1 : mbE0;
            MB_ARRIVE(mb);
        }

        float ownA = gp ? vA2 : vA;
        float ownB = gp ? vB2 : vB;
        float sndA = gp ? vA  : vA2;
        float sndB = gp ? vB  : vB2;
        float rcvA = __shfl_xor_sync(0xFFFFFFFFu, sndA, 1);
        float rcvB = __shfl_xor_sync(0xFFFFFFFFu, sndB, 1);
        float F = gp ? rcvB : ownB;
        float O = gp ? ownB : rcvB;
        if (act) cm = fmaf(F, cm, ownA * rcvA);
        float hm = O * tanhap(cm);

        // A gate: layer-4 lanes wait for B's read of the buffer they overwrite
        if (isL4) {
            const unsigned mb = (par ^ 1) ? mbE1 : mbE0;
            MB_WAIT(mb, (((scur + 1) >> 1) + 1) & 1);
        }

        if (act && real) {
            z[par ^ 1][l][em][10 + u] = hm;
            if (l < L_ - 1) {
                z[par ^ 1][l + 1][em][u] = hm;
            } else {
                out[((size_t)t * B_ + bm) * H_ + u] = hm;
            }
            if (!ST && t == T_ - 1) {
                out[base_hn + ((size_t)l * B_ + bm) * H_ + u] = hm;
                out[base_cn + ((size_t)l * B_ + bm) * H_ + u] = cm;
            }
        }
        if (ldrGo)
            z[par ^ 1][0][em][u] = xl;

        // layer-4 store published to B
        if (isL4) {
            const unsigned mb = (par ^ 1) ? mbF1 : mbF0;
            MB_ARRIVE(mb);
        }
    };

    // ---- ramp-up: s = 0..9 ----
    for (int s = 0; s < L_; ++s)
        stepf(s, s & 1, BoolC<false>{});

    // ---- steady: s = 10..1021 ----
    for (int s0 = L_; s0 < T_ - 2; s0 += 2) {
        stepf(s0,     0, BoolC<true>{});
        stepf(s0 + 1, 1, BoolC<true>{});
    }

    // ---- ramp-down: s = 1022..1033 ----
    for (int s = T_ - 2; s < T_ + L_; ++s)
        stepf(s, s & 1, BoolC<false>{});
}

extern "C" void kernel_launch(void* const* d_in, const int* in_sizes, int n_in,
                              void* d_out, int out_size) {
    const float* x   = (const float*)d_in[0];
    const float* hp  = (const float*)d_in[1];
    const float* cp  = (const float*)d_in[2];
    const float* Wih = (const float*)d_in[3];
    const float* Whh = (const float*)d_in[4];
    const float* bih = (const float*)d_in[5];
    const float* bhh = (const float*)d_in[6];
    float* out = (float*)d_out;

    dim3 grid(B_ / NB);   // 256 blocks; 2 CTAs/SM -> 4 sync domains per SM
    dim3 block(NTH);      // 448 threads = 14 warps (2 groups of 7)
    lstm_pipe14<<<grid, block>>>(x, hp, cp, Wih, Whh, bih, bhh, out);
}